// round 14
// baseline (speedup 1.0000x reference)
#include <cuda_runtime.h>
#include <cstdint>

#define Bt   128
#define Tt   512
#define Et   256
#define Ht   512
#define VCt  64
#define VPt  128
#define NCTA 128
#define NTHR 1024

// ---------------- persistent device scratch ----------------
__device__ float g_P[VCt * Ht];
__device__ int g_srcT[Tt * Bt];      // src transposed: [t][b]
__device__ float g_h0[2][Ht * Bt];   // [j][b]
__device__ float g_h1[2][Ht * Bt];
__device__ float g_ysT[(size_t)Tt * Ht * Bt];
__device__ unsigned g_count = 0;
__device__ unsigned g_sense = 0;

// ---------------- kernel 0: transpose src to [t][b] ----------------
__global__ __launch_bounds__(256) void srcT_kernel(const int* __restrict__ src) {
  int i = blockIdx.x * 256 + threadIdx.x;   // 65536 elements
  int b = i >> 9, t = i & 511;
  g_srcT[t * Bt + b] = src[i];
}

// ---------------- kernel 1: P = emb_table @ W_xh0 + b_xh0 ----------------
__global__ __launch_bounds__(128) void proj_kernel(
    const float* __restrict__ emb, const float* __restrict__ Wxh0,
    const float* __restrict__ bxh0) {
  __shared__ float esh[Et];
  int v = blockIdx.x;
  for (int i = threadIdx.x; i < Et; i += 128) esh[i] = emb[v * Et + i];
  __syncthreads();
  int j = threadIdx.x + blockIdx.y * 128;
  float s = bxh0[j];
#pragma unroll 8
  for (int e = 0; e < Et; ++e) s = fmaf(esh[e], Wxh0[e * Ht + j], s);
  g_P[v * Ht + j] = s;
}

__device__ __forceinline__ void fma16(float4& a0, float4& a1, float4& a2,
                                      float4& a3, const float4 w,
                                      const float4 hv) {
  a0.x = fmaf(w.x, hv.x, a0.x); a0.y = fmaf(w.x, hv.y, a0.y);
  a0.z = fmaf(w.x, hv.z, a0.z); a0.w = fmaf(w.x, hv.w, a0.w);
  a1.x = fmaf(w.y, hv.x, a1.x); a1.y = fmaf(w.y, hv.y, a1.y);
  a1.z = fmaf(w.y, hv.z, a1.z); a1.w = fmaf(w.y, hv.w, a1.w);
  a2.x = fmaf(w.z, hv.x, a2.x); a2.y = fmaf(w.z, hv.y, a2.y);
  a2.z = fmaf(w.z, hv.z, a2.z); a2.w = fmaf(w.z, hv.w, a2.w);
  a3.x = fmaf(w.w, hv.x, a3.x); a3.y = fmaf(w.w, hv.y, a3.y);
  a3.z = fmaf(w.w, hv.z, a3.z); a3.w = fmaf(w.w, hv.w, a3.w);
}

// ---------------- kernel 2: persistent recurrent kernel ----------------
// 128 CTAs x 1024 threads (32 warps). CTA owns cols jb..jb+3 of h0 AND h1.
// Warp s owns k-slice of 16 -> 8 eligible warps per SMSP to hide L2 latency.
// One grid barrier per step (R4's proven counter+sense barrier).
__global__ __launch_bounds__(NTHR, 1) void rec_kernel(
    const int* __restrict__ lens,
    const float* __restrict__ Whh0, const float* __restrict__ Wxh1,
    const float* __restrict__ bxh1, const float* __restrict__ Whh1) {
  extern __shared__ char dsm[];
  float4* Wsh0 = (float4*)dsm;         // [512 k]{c0..c3}  8 KB (Whh0)
  float4* Wsh1 = Wsh0 + Ht;            // Wxh1
  float4* Wsh2 = Wsh1 + Ht;            // Whh1
  float4* red4 = Wsh2 + Ht;            // [32 s][8 g][32 bt] 128 KB
  float* Psh = (float*)(red4 + 8192);  // [64 v][4 c]  1 KB

  __shared__ int srcsh[Bt];
  __shared__ int lensh[Bt];
  __shared__ float bsh[4];
  __shared__ unsigned s_sense;

  const int tid = threadIdx.x;
  const int jb = blockIdx.x * 4;

  for (int i = tid; i < Ht * 4; i += NTHR) {
    int k = i >> 2, c = i & 3;
    ((float*)Wsh0)[i] = Whh0[k * Ht + jb + c];
    ((float*)Wsh1)[i] = Wxh1[k * Ht + jb + c];
    ((float*)Wsh2)[i] = Whh1[k * Ht + jb + c];
  }
  for (int i = tid; i < VCt * 4; i += NTHR) {
    int v = i >> 2, c = i & 3;
    Psh[i] = g_P[v * Ht + jb + c];
  }
  if (tid < Bt) lensh[tid] = lens[tid];
  if (tid < 4) bsh[tid] = bxh1[jb + tid];
  // h1(-1) = 0 in buffer 1 (own cols only)
  if (tid < 512) {
    int c = tid >> 7, b = tid & 127;
    g_h1[1][(jb + c) * Bt + b] = 0.f;
  }
  __syncthreads();
  // prologue: h0(0) = mask0 ? tanh(P[tok0]) : 0  -> buffer 0
  if (tid < 512) {
    int c = tid >> 7, b = tid & 127;
    int tok = g_srcT[b];  // t = 0
    float a = Psh[tok * 4 + c];
    g_h0[0][(jb + c) * Bt + b] = (0 < lensh[b]) ? tanhf(a) : 0.f;
  }
  if (tid == 0) s_sense = *(volatile unsigned*)&g_sense;
  __syncthreads();

#define GBAR()                                              \
  do {                                                      \
    __syncthreads();                                        \
    if (tid == 0) {                                         \
      unsigned ns = s_sense ^ 1u;                           \
      __threadfence();                                      \
      unsigned old = atomicAdd(&g_count, 1u);               \
      if (old == (unsigned)(NCTA - 1)) {                    \
        g_count = 0u;                                       \
        __threadfence();                                    \
        *(volatile unsigned*)&g_sense = ns;                 \
      } else {                                              \
        while (*(volatile unsigned*)&g_sense != ns)         \
          __nanosleep(20);                                  \
      }                                                     \
      __threadfence();                                      \
      s_sense = ns;                                         \
    }                                                       \
    __syncthreads();                                        \
  } while (0)

  GBAR();  // h0(0), h1(-1) visible everywhere; srcT ready (kernel order)

  const int bt = tid & 31;   // 4 b's: b = 4*bt .. 4*bt+3
  const int s = tid >> 5;    // k-slice of 16 (32 warps)

  for (int t = 0; t < Tt; ++t) {
    const int p = t & 1;
    const float4* H0 = (const float4*)g_h0[p];        // h0(t)
    const float4* H1p = (const float4*)g_h1[p ^ 1];   // h1(t-1)
    float* h0n = g_h0[p ^ 1];                         // h0(t+1)
    float* h1c = g_h1[p];                             // h1(t)

    if (tid < Bt) {
      int tn = (t + 1 < Tt) ? t + 1 : Tt - 1;
      srcsh[tid] = g_srcT[tn * Bt + tid];             // coalesced
    }

    // ---- fused GEMMs: accN = h0(t)@Whh0 ; accO = h0(t)@Wxh1 + h1(t-1)@Whh1
    {
      float4 z = make_float4(0, 0, 0, 0);
      float4 n0 = z, n1 = z, n2 = z, n3 = z;
      float4 o0 = z, o1 = z, o2 = z, o3 = z;
#pragma unroll 4
      for (int kk = 0; kk < 16; ++kk) {
        int k = s * 16 + kk;
        float4 ha = H0[k * 32 + bt];
        float4 hb = H1p[k * 32 + bt];
        float4 w0 = Wsh0[k];
        float4 w1 = Wsh1[k];
        float4 w2 = Wsh2[k];
        fma16(n0, n1, n2, n3, w0, ha);
        fma16(o0, o1, o2, o3, w1, ha);
        fma16(o0, o1, o2, o3, w2, hb);
      }
      red4[s * 256 + 0 * 32 + bt] = n0;
      red4[s * 256 + 1 * 32 + bt] = n1;
      red4[s * 256 + 2 * 32 + bt] = n2;
      red4[s * 256 + 3 * 32 + bt] = n3;
      red4[s * 256 + 4 * 32 + bt] = o0;
      red4[s * 256 + 5 * 32 + bt] = o1;
      red4[s * 256 + 6 * 32 + bt] = o2;
      red4[s * 256 + 7 * 32 + bt] = o3;
    }
    __syncthreads();

    // ---- reduce (tid < 256): thread -> group g (phase*4+c), bt2, 4 b's ----
    if (tid < 256) {
      int g = tid >> 5, bt2 = tid & 31;
      int b0 = bt2 * 4;
      float4 sm = red4[g * 32 + bt2];
#pragma unroll
      for (int s2 = 1; s2 < 32; ++s2) {
        float4 r = red4[s2 * 256 + g * 32 + bt2];
        sm.x += r.x; sm.y += r.y; sm.z += r.z; sm.w += r.w;
      }
      int l0 = lensh[b0], l1 = lensh[b0 + 1], l2 = lensh[b0 + 2],
          l3 = lensh[b0 + 3];
      if (g < 4) {  // h0(t+1)
        int c = g;
        sm.x += Psh[srcsh[b0] * 4 + c];
        sm.y += Psh[srcsh[b0 + 1] * 4 + c];
        sm.z += Psh[srcsh[b0 + 2] * 4 + c];
        sm.w += Psh[srcsh[b0 + 3] * 4 + c];
        const float* h0cur = g_h0[p];
        float4 prev = *(const float4*)&h0cur[(jb + c) * Bt + b0];
        float4 nv;
        nv.x = (t + 1 < l0) ? tanhf(sm.x) : prev.x;
        nv.y = (t + 1 < l1) ? tanhf(sm.y) : prev.y;
        nv.z = (t + 1 < l2) ? tanhf(sm.z) : prev.z;
        nv.w = (t + 1 < l3) ? tanhf(sm.w) : prev.w;
        *(float4*)&h0n[(jb + c) * Bt + b0] = nv;
      } else {  // h1(t) + ys(t)
        int c = g - 4;
        float bv = bsh[c];
        sm.x += bv; sm.y += bv; sm.z += bv; sm.w += bv;
        const float* h1prv = g_h1[p ^ 1];
        float4 prev = *(const float4*)&h1prv[(jb + c) * Bt + b0];
        float4 nv;
        nv.x = (t < l0) ? tanhf(sm.x) : prev.x;
        nv.y = (t < l1) ? tanhf(sm.y) : prev.y;
        nv.z = (t < l2) ? tanhf(sm.z) : prev.z;
        nv.w = (t < l3) ? tanhf(sm.w) : prev.w;
        *(float4*)&h1c[(jb + c) * Bt + b0] = nv;
        float* ys = g_ysT + (size_t)t * (Ht * Bt);
        *(float4*)&ys[(jb + c) * Bt + b0] = nv;
      }
    }
    GBAR();  // publish h0(t+1), h1(t), ys(t); protects red/srcsh reuse
  }
#undef GBAR
}

// ---------------- kernel 3: logits = ys @ fc_w + fc_b ----------------
__global__ __launch_bounds__(256) void fc_kernel(const float* __restrict__ fcw,
                                                 const float* __restrict__ fcb,
                                                 float* __restrict__ out) {
  __shared__ float4 Ash[32 * 32];
  __shared__ float4 Bsh[32 * 16];
  const int t = blockIdx.y;
  const int pt = blockIdx.x;
  const int tid = threadIdx.x;
  const int pq = tid & 15;
  const int bq = tid >> 4;
  const float4* ys4 = (const float4*)g_ysT + (size_t)t * (Ht * Bt / 4);
  const float4* w4 = (const float4*)fcw;

  float4 acc[8];
#pragma unroll
  for (int i = 0; i < 8; ++i) acc[i] = make_float4(0, 0, 0, 0);

  for (int k0 = 0; k0 < Ht; k0 += 32) {
#pragma unroll
    for (int i = 0; i < 4; ++i) {
      int idx = tid + i * 256;
      int kk = idx >> 5, b4 = idx & 31;
      Ash[idx] = ys4[(k0 + kk) * 32 + b4];
    }
#pragma unroll
    for (int i = 0; i < 2; ++i) {
      int idx = tid + i * 256;
      int kk = idx >> 4, p4 = idx & 15;
      Bsh[idx] = w4[(k0 + kk) * (VPt / 4) + pt * 16 + p4];
    }
    __syncthreads();
#pragma unroll
    for (int kk = 0; kk < 32; ++kk) {
      float4 wv = Bsh[kk * 16 + pq];
      float4 hA = Ash[kk * 32 + bq * 2];
      float4 hB = Ash[kk * 32 + bq * 2 + 1];
      float hb[8] = {hA.x, hA.y, hA.z, hA.w, hB.x, hB.y, hB.z, hB.w};
#pragma unroll
      for (int i = 0; i < 8; ++i) {
        acc[i].x = fmaf(hb[i], wv.x, acc[i].x);
        acc[i].y = fmaf(hb[i], wv.y, acc[i].y);
        acc[i].z = fmaf(hb[i], wv.z, acc[i].z);
        acc[i].w = fmaf(hb[i], wv.w, acc[i].w);
      }
    }
    __syncthreads();
  }
  float4 bv = ((const float4*)fcb)[pt * 16 + pq];
  float4* out4 = (float4*)out;
#pragma unroll
  for (int i = 0; i < 8; ++i) {
    int b = bq * 8 + i;
    float4 v;
    v.x = acc[i].x + bv.x;
    v.y = acc[i].y + bv.y;
    v.z = acc[i].z + bv.z;
    v.w = acc[i].w + bv.w;
    out4[((size_t)b * Tt + t) * (VPt / 4) + pt * 16 + pq] = v;
  }
}

extern "C" void kernel_launch(void* const* d_in, const int* in_sizes, int n_in,
                              void* d_out, int out_size) {
  const int* src = (const int*)d_in[0];
  const int* lens = (const int*)d_in[1];
  const float* emb = (const float*)d_in[2];
  const float* Wxh0 = (const float*)d_in[3];
  const float* bxh0 = (const float*)d_in[4];
  const float* Whh0 = (const float*)d_in[5];
  const float* Wxh1 = (const float*)d_in[6];
  const float* bxh1 = (const float*)d_in[7];
  const float* Whh1 = (const float*)d_in[8];
  const float* fcw = (const float*)d_in[9];
  const float* fcb = (const float*)d_in[10];

  const int smem_bytes = 3 * 8192 + 131072 + 1024;  // 156672
  cudaFuncSetAttribute(rec_kernel, cudaFuncAttributeMaxDynamicSharedMemorySize,
                       smem_bytes);

  srcT_kernel<<<256, 256>>>(src);
  proj_kernel<<<dim3(VCt, 4), 128>>>(emb, Wxh0, bxh0);
  rec_kernel<<<NCTA, NTHR, smem_bytes>>>(lens, Whh0, Wxh1, bxh1, Whh1);
  fc_kernel<<<dim3(2, Tt), 256>>>(fcw, fcb, (float*)d_out);
}

// round 15
// speedup vs baseline: 1.0781x; 1.0781x over previous
#include <cuda_runtime.h>
#include <cstdint>

#define Bt   128
#define Tt   512
#define Et   256
#define Ht   512
#define VCt  64
#define VPt  128
#define NCTA 128
#define NTHR 512

// ---------------- persistent device scratch ----------------
__device__ float g_P[VCt * Ht];
__device__ int g_srcT[Tt * Bt];      // src transposed: [t][b]
__device__ float g_h0[2][Ht * Bt];   // [j][b]
__device__ float g_h1[2][Ht * Bt];
__device__ float g_ysT[(size_t)Tt * Ht * Bt];
__device__ unsigned g_count = 0;
__device__ unsigned g_sense = 0;

// ---------------- kernel 0: transpose src to [t][b] ----------------
__global__ __launch_bounds__(256) void srcT_kernel(const int* __restrict__ src) {
  int i = blockIdx.x * 256 + threadIdx.x;   // 65536 elements
  int b = i >> 9, t = i & 511;
  g_srcT[t * Bt + b] = src[i];
}

// ---------------- kernel 1: P = emb_table @ W_xh0 + b_xh0 ----------------
__global__ __launch_bounds__(128) void proj_kernel(
    const float* __restrict__ emb, const float* __restrict__ Wxh0,
    const float* __restrict__ bxh0) {
  __shared__ float esh[Et];
  int v = blockIdx.x;
  for (int i = threadIdx.x; i < Et; i += 128) esh[i] = emb[v * Et + i];
  __syncthreads();
  int j = threadIdx.x + blockIdx.y * 128;
  float s = bxh0[j];
#pragma unroll 8
  for (int e = 0; e < Et; ++e) s = fmaf(esh[e], Wxh0[e * Ht + j], s);
  g_P[v * Ht + j] = s;
}

__device__ __forceinline__ void fma16(float4& a0, float4& a1, float4& a2,
                                      float4& a3, const float4 w,
                                      const float4 hv) {
  a0.x = fmaf(w.x, hv.x, a0.x); a0.y = fmaf(w.x, hv.y, a0.y);
  a0.z = fmaf(w.x, hv.z, a0.z); a0.w = fmaf(w.x, hv.w, a0.w);
  a1.x = fmaf(w.y, hv.x, a1.x); a1.y = fmaf(w.y, hv.y, a1.y);
  a1.z = fmaf(w.y, hv.z, a1.z); a1.w = fmaf(w.y, hv.w, a1.w);
  a2.x = fmaf(w.z, hv.x, a2.x); a2.y = fmaf(w.z, hv.y, a2.y);
  a2.z = fmaf(w.z, hv.z, a2.z); a2.w = fmaf(w.z, hv.w, a2.w);
  a3.x = fmaf(w.w, hv.x, a3.x); a3.y = fmaf(w.w, hv.y, a3.y);
  a3.z = fmaf(w.w, hv.z, a3.z); a3.w = fmaf(w.w, hv.w, a3.w);
}

// ---------------- kernel 2: persistent recurrent kernel ----------------
// 128 CTAs x 512 threads (16 warps — measured optimum). CTA owns cols
// jb..jb+3 of h0 AND h1. Warp s owns k-slice of 32; unroll 8 doubles
// per-warp MLP against L2 latency. One grid barrier per step.
__global__ __launch_bounds__(NTHR, 1) void rec_kernel(
    const int* __restrict__ lens,
    const float* __restrict__ Whh0, const float* __restrict__ Wxh1,
    const float* __restrict__ bxh1, const float* __restrict__ Whh1) {
  extern __shared__ char dsm[];
  float4* Wsh0 = (float4*)dsm;         // [512 k]{c0..c3}  8 KB (Whh0)
  float4* Wsh1 = Wsh0 + Ht;            // Wxh1
  float4* Wsh2 = Wsh1 + Ht;            // Whh1
  float4* red4 = Wsh2 + Ht;            // [16 s][8 g][32 bt] 64 KB
  float* Psh = (float*)(red4 + 4096);  // [64 v][4 c]  1 KB

  __shared__ int srcsh[Bt];
  __shared__ int lensh[Bt];
  __shared__ float bsh[4];
  __shared__ unsigned s_sense;

  const int tid = threadIdx.x;
  const int jb = blockIdx.x * 4;

  for (int i = tid; i < Ht * 4; i += NTHR) {
    int k = i >> 2, c = i & 3;
    ((float*)Wsh0)[i] = Whh0[k * Ht + jb + c];
    ((float*)Wsh1)[i] = Wxh1[k * Ht + jb + c];
    ((float*)Wsh2)[i] = Whh1[k * Ht + jb + c];
  }
  for (int i = tid; i < VCt * 4; i += NTHR) {
    int v = i >> 2, c = i & 3;
    Psh[i] = g_P[v * Ht + jb + c];
  }
  if (tid < Bt) lensh[tid] = lens[tid];
  if (tid < 4) bsh[tid] = bxh1[jb + tid];
  __syncthreads();
  // h1(-1) = 0 in buffer 1; h0(0) = mask0 ? tanh(P[tok0]) : 0
  if (tid < 512) {
    int c = tid >> 7, b = tid & 127;
    g_h1[1][(jb + c) * Bt + b] = 0.f;
    int tok = g_srcT[b];  // t = 0 (srcT_kernel ordered before this launch)
    float a = Psh[tok * 4 + c];
    g_h0[0][(jb + c) * Bt + b] = (0 < lensh[b]) ? tanhf(a) : 0.f;
  }
  if (tid == 0) s_sense = *(volatile unsigned*)&g_sense;
  __syncthreads();

#define GBAR()                                              \
  do {                                                      \
    __syncthreads();                                        \
    if (tid == 0) {                                         \
      unsigned ns = s_sense ^ 1u;                           \
      __threadfence();                                      \
      unsigned old = atomicAdd(&g_count, 1u);               \
      if (old == (unsigned)(NCTA - 1)) {                    \
        g_count = 0u;                                       \
        __threadfence();                                    \
        *(volatile unsigned*)&g_sense = ns;                 \
      } else {                                              \
        while (*(volatile unsigned*)&g_sense != ns)         \
          __nanosleep(20);                                  \
      }                                                     \
      __threadfence();                                      \
      s_sense = ns;                                         \
    }                                                       \
    __syncthreads();                                        \
  } while (0)

  GBAR();  // h0(0), h1(-1) visible everywhere

  const int bt = tid & 31;   // 4 b's: b = 4*bt .. 4*bt+3
  const int s = tid >> 5;    // k-slice of 32 (16 warps)

  for (int t = 0; t < Tt; ++t) {
    const int p = t & 1;
    const float4* H0 = (const float4*)g_h0[p];        // h0(t)
    const float4* H1p = (const float4*)g_h1[p ^ 1];   // h1(t-1)
    float* h0n = g_h0[p ^ 1];                         // h0(t+1)
    float* h1c = g_h1[p];                             // h1(t)

    if (tid < Bt) {
      int tn = (t + 1 < Tt) ? t + 1 : Tt - 1;
      srcsh[tid] = g_srcT[tn * Bt + tid];             // coalesced
    }

    // ---- fused GEMMs: accN = h0(t)@Whh0 ; accO = h0(t)@Wxh1 + h1(t-1)@Whh1
    {
      float4 z = make_float4(0, 0, 0, 0);
      float4 n0 = z, n1 = z, n2 = z, n3 = z;
      float4 o0 = z, o1 = z, o2 = z, o3 = z;
#pragma unroll 8
      for (int kk = 0; kk < 32; ++kk) {
        int k = s * 32 + kk;
        float4 ha = H0[k * 32 + bt];
        float4 hb = H1p[k * 32 + bt];
        float4 w0 = Wsh0[k];
        float4 w1 = Wsh1[k];
        float4 w2 = Wsh2[k];
        fma16(n0, n1, n2, n3, w0, ha);
        fma16(o0, o1, o2, o3, w1, ha);
        fma16(o0, o1, o2, o3, w2, hb);
      }
      red4[s * 256 + 0 * 32 + bt] = n0;
      red4[s * 256 + 1 * 32 + bt] = n1;
      red4[s * 256 + 2 * 32 + bt] = n2;
      red4[s * 256 + 3 * 32 + bt] = n3;
      red4[s * 256 + 4 * 32 + bt] = o0;
      red4[s * 256 + 5 * 32 + bt] = o1;
      red4[s * 256 + 6 * 32 + bt] = o2;
      red4[s * 256 + 7 * 32 + bt] = o3;
    }
    __syncthreads();

    // ---- reduce (tid < 256): thread -> group g (phase*4+c), bt2, 4 b's ----
    if (tid < 256) {
      int g = tid >> 5, bt2 = tid & 31;
      int b0 = bt2 * 4;
      float4 sm = red4[g * 32 + bt2];
#pragma unroll
      for (int s2 = 1; s2 < 16; ++s2) {
        float4 r = red4[s2 * 256 + g * 32 + bt2];
        sm.x += r.x; sm.y += r.y; sm.z += r.z; sm.w += r.w;
      }
      int l0 = lensh[b0], l1 = lensh[b0 + 1], l2 = lensh[b0 + 2],
          l3 = lensh[b0 + 3];
      if (g < 4) {  // h0(t+1)
        int c = g;
        sm.x += Psh[srcsh[b0] * 4 + c];
        sm.y += Psh[srcsh[b0 + 1] * 4 + c];
        sm.z += Psh[srcsh[b0 + 2] * 4 + c];
        sm.w += Psh[srcsh[b0 + 3] * 4 + c];
        const float* h0cur = g_h0[p];
        float4 prev = *(const float4*)&h0cur[(jb + c) * Bt + b0];
        float4 nv;
        nv.x = (t + 1 < l0) ? tanhf(sm.x) : prev.x;
        nv.y = (t + 1 < l1) ? tanhf(sm.y) : prev.y;
        nv.z = (t + 1 < l2) ? tanhf(sm.z) : prev.z;
        nv.w = (t + 1 < l3) ? tanhf(sm.w) : prev.w;
        *(float4*)&h0n[(jb + c) * Bt + b0] = nv;
      } else {  // h1(t) + ys(t)
        int c = g - 4;
        float bv = bsh[c];
        sm.x += bv; sm.y += bv; sm.z += bv; sm.w += bv;
        const float* h1prv = g_h1[p ^ 1];
        float4 prev = *(const float4*)&h1prv[(jb + c) * Bt + b0];
        float4 nv;
        nv.x = (t < l0) ? tanhf(sm.x) : prev.x;
        nv.y = (t < l1) ? tanhf(sm.y) : prev.y;
        nv.z = (t < l2) ? tanhf(sm.z) : prev.z;
        nv.w = (t < l3) ? tanhf(sm.w) : prev.w;
        *(float4*)&h1c[(jb + c) * Bt + b0] = nv;
        float* ys = g_ysT + (size_t)t * (Ht * Bt);
        *(float4*)&ys[(jb + c) * Bt + b0] = nv;
      }
    }
    GBAR();  // publish h0(t+1), h1(t), ys(t); protects red/srcsh reuse
  }
#undef GBAR
}

// ---------------- kernel 3: logits = ys @ fc_w + fc_b ----------------
__global__ __launch_bounds__(256) void fc_kernel(const float* __restrict__ fcw,
                                                 const float* __restrict__ fcb,
                                                 float* __restrict__ out) {
  __shared__ float4 Ash[32 * 32];
  __shared__ float4 Bsh[32 * 16];
  const int t = blockIdx.y;
  const int pt = blockIdx.x;
  const int tid = threadIdx.x;
  const int pq = tid & 15;
  const int bq = tid >> 4;
  const float4* ys4 = (const float4*)g_ysT + (size_t)t * (Ht * Bt / 4);
  const float4* w4 = (const float4*)fcw;

  float4 acc[8];
#pragma unroll
  for (int i = 0; i < 8; ++i) acc[i] = make_float4(0, 0, 0, 0);

  for (int k0 = 0; k0 < Ht; k0 += 32) {
#pragma unroll
    for (int i = 0; i < 4; ++i) {
      int idx = tid + i * 256;
      int kk = idx >> 5, b4 = idx & 31;
      Ash[idx] = ys4[(k0 + kk) * 32 + b4];
    }
#pragma unroll
    for (int i = 0; i < 2; ++i) {
      int idx = tid + i * 256;
      int kk = idx >> 4, p4 = idx & 15;
      Bsh[idx] = w4[(k0 + kk) * (VPt / 4) + pt * 16 + p4];
    }
    __syncthreads();
#pragma unroll
    for (int kk = 0; kk < 32; ++kk) {
      float4 wv = Bsh[kk * 16 + pq];
      float4 hA = Ash[kk * 32 + bq * 2];
      float4 hB = Ash[kk * 32 + bq * 2 + 1];
      float hb[8] = {hA.x, hA.y, hA.z, hA.w, hB.x, hB.y, hB.z, hB.w};
#pragma unroll
      for (int i = 0; i < 8; ++i) {
        acc[i].x = fmaf(hb[i], wv.x, acc[i].x);
        acc[i].y = fmaf(hb[i], wv.y, acc[i].y);
        acc[i].z = fmaf(hb[i], wv.z, acc[i].z);
        acc[i].w = fmaf(hb[i], wv.w, acc[i].w);
      }
    }
    __syncthreads();
  }
  float4 bv = ((const float4*)fcb)[pt * 16 + pq];
  float4* out4 = (float4*)out;
#pragma unroll
  for (int i = 0; i < 8; ++i) {
    int b = bq * 8 + i;
    float4 v;
    v.x = acc[i].x + bv.x;
    v.y = acc[i].y + bv.y;
    v.z = acc[i].z + bv.z;
    v.w = acc[i].w + bv.w;
    out4[((size_t)b * Tt + t) * (VPt / 4) + pt * 16 + pq] = v;
  }
}

extern "C" void kernel_launch(void* const* d_in, const int* in_sizes, int n_in,
                              void* d_out, int out_size) {
  const int* src = (const int*)d_in[0];
  const int* lens = (const int*)d_in[1];
  const float* emb = (const float*)d_in[2];
  const float* Wxh0 = (const float*)d_in[3];
  const float* bxh0 = (const float*)d_in[4];
  const float* Whh0 = (const float*)d_in[5];
  const float* Wxh1 = (const float*)d_in[6];
  const float* bxh1 = (const float*)d_in[7];
  const float* Whh1 = (const float*)d_in[8];
  const float* fcw = (const float*)d_in[9];
  const float* fcb = (const float*)d_in[10];

  const int smem_bytes = 3 * 8192 + 65536 + 1024;  // 91136
  cudaFuncSetAttribute(rec_kernel, cudaFuncAttributeMaxDynamicSharedMemorySize,
                       smem_bytes);

  srcT_kernel<<<256, 256>>>(src);
  proj_kernel<<<dim3(VCt, 4), 128>>>(emb, Wxh0, bxh0);
  rec_kernel<<<NCTA, NTHR, smem_bytes>>>(lens, Whh0, Wxh1, bxh1, Whh1);
  fc_kernel<<<dim3(2, Tt), 256>>>(fcw, fcb, (float*)d_out);
}

// round 17
// speedup vs baseline: 1.1135x; 1.0328x over previous
#include <cuda_runtime.h>
#include <cstdint>

#define Bt   128
#define Tt   512
#define Et   256
#define Ht   512
#define VCt  64
#define VPt  128
#define NCTA 128
#define NTHR 512

// ---------------- persistent device scratch ----------------
__device__ float g_P[VCt * Ht];
__device__ int g_srcT[Tt * Bt];      // src transposed: [t][b]
__device__ float g_h0[2][Ht * Bt];   // [j][b]
__device__ float g_h1[2][Ht * Bt];
__device__ float g_ysT[(size_t)Tt * Ht * Bt];
__device__ unsigned g_count = 0;
__device__ unsigned g_sense = 0;

// ---------------- kernel 0: transpose src to [t][b] ----------------
__global__ __launch_bounds__(256) void srcT_kernel(const int* __restrict__ src) {
  int i = blockIdx.x * 256 + threadIdx.x;   // 65536 elements
  int b = i >> 9, t = i & 511;
  g_srcT[t * Bt + b] = src[i];
}

// ---------------- kernel 1: P = emb_table @ W_xh0 + b_xh0 ----------------
__global__ __launch_bounds__(128) void proj_kernel(
    const float* __restrict__ emb, const float* __restrict__ Wxh0,
    const float* __restrict__ bxh0) {
  __shared__ float esh[Et];
  int v = blockIdx.x;
  for (int i = threadIdx.x; i < Et; i += 128) esh[i] = emb[v * Et + i];
  __syncthreads();
  int j = threadIdx.x + blockIdx.y * 128;
  float s = bxh0[j];
#pragma unroll 8
  for (int e = 0; e < Et; ++e) s = fmaf(esh[e], Wxh0[e * Ht + j], s);
  g_P[v * Ht + j] = s;
}

__device__ __forceinline__ void fma16(float4& a0, float4& a1, float4& a2,
                                      float4& a3, const float4 w,
                                      const float4 hv) {
  a0.x = fmaf(w.x, hv.x, a0.x); a0.y = fmaf(w.x, hv.y, a0.y);
  a0.z = fmaf(w.x, hv.z, a0.z); a0.w = fmaf(w.x, hv.w, a0.w);
  a1.x = fmaf(w.y, hv.x, a1.x); a1.y = fmaf(w.y, hv.y, a1.y);
  a1.z = fmaf(w.y, hv.z, a1.z); a1.w = fmaf(w.y, hv.w, a1.w);
  a2.x = fmaf(w.z, hv.x, a2.x); a2.y = fmaf(w.z, hv.y, a2.y);
  a2.z = fmaf(w.z, hv.z, a2.z); a2.w = fmaf(w.z, hv.w, a2.w);
  a3.x = fmaf(w.w, hv.x, a3.x); a3.y = fmaf(w.w, hv.y, a3.y);
  a3.z = fmaf(w.w, hv.z, a3.z); a3.w = fmaf(w.w, hv.w, a3.w);
}

// ---------------- kernel 2: persistent recurrent kernel ----------------
// 128 CTAs x 512 threads (16 warps). CTA owns cols jb..jb+3 of h0 AND h1.
// Warp s owns k-slice of 32; unroll 8. One grid barrier per step.
// Tail trimmed: ys store deferred past the barrier; freeze values carried
// in registers (no L2 reload on the critical path).
__global__ __launch_bounds__(NTHR, 1) void rec_kernel(
    const int* __restrict__ lens,
    const float* __restrict__ Whh0, const float* __restrict__ Wxh1,
    const float* __restrict__ bxh1, const float* __restrict__ Whh1) {
  extern __shared__ char dsm[];
  float4* Wsh0 = (float4*)dsm;         // [512 k]{c0..c3}  8 KB (Whh0)
  float4* Wsh1 = Wsh0 + Ht;            // Wxh1
  float4* Wsh2 = Wsh1 + Ht;            // Whh1
  float4* red4 = Wsh2 + Ht;            // [16 s][8 g][32 bt] 64 KB
  float* Psh = (float*)(red4 + 4096);  // [64 v][4 c]  1 KB

  __shared__ int srcsh[Bt];
  __shared__ int lensh[Bt];
  __shared__ float bsh[4];
  __shared__ unsigned s_sense;

  const int tid = threadIdx.x;
  const int jb = blockIdx.x * 4;

  for (int i = tid; i < Ht * 4; i += NTHR) {
    int k = i >> 2, c = i & 3;
    ((float*)Wsh0)[i] = Whh0[k * Ht + jb + c];
    ((float*)Wsh1)[i] = Wxh1[k * Ht + jb + c];
    ((float*)Wsh2)[i] = Whh1[k * Ht + jb + c];
  }
  for (int i = tid; i < VCt * 4; i += NTHR) {
    int v = i >> 2, c = i & 3;
    Psh[i] = g_P[v * Ht + jb + c];
  }
  if (tid < Bt) lensh[tid] = lens[tid];
  if (tid < 4) bsh[tid] = bxh1[jb + tid];
  __syncthreads();
  // h1(-1) = 0 in buffer 1; h0(0) = mask0 ? tanh(P[tok0]) : 0
  if (tid < 512) {
    int c = tid >> 7, b = tid & 127;
    g_h1[1][(jb + c) * Bt + b] = 0.f;
    int tok = g_srcT[b];  // t = 0 (srcT_kernel ordered before this launch)
    float a = Psh[tok * 4 + c];
    g_h0[0][(jb + c) * Bt + b] = (0 < lensh[b]) ? tanhf(a) : 0.f;
  }
  if (tid == 0) s_sense = *(volatile unsigned*)&g_sense;
  __syncthreads();

  // register-carried freeze values for the reduce threads (tid < 256):
  // g<4: thread owns h0[jb+g][b0..b0+3]; g>=4: h1[jb+g-4][b0..b0+3]
  float4 prevReg = make_float4(0.f, 0.f, 0.f, 0.f);
  float4 ysReg = make_float4(0.f, 0.f, 0.f, 0.f);
  if (tid < 256) {
    int g = tid >> 5, bt2 = tid & 31, b0 = bt2 * 4;
    if (g < 4)
      prevReg = *(const float4*)&g_h0[0][(jb + g) * Bt + b0];  // h0(0), own cols
    // g>=4: h1(-1) = 0 already in prevReg
  }

#define GBAR()                                              \
  do {                                                      \
    __syncthreads();                                        \
    if (tid == 0) {                                         \
      unsigned ns = s_sense ^ 1u;                           \
      __threadfence();                                      \
      unsigned old = atomicAdd(&g_count, 1u);               \
      if (old == (unsigned)(NCTA - 1)) {                    \
        g_count = 0u;                                       \
        __threadfence();                                    \
        *(volatile unsigned*)&g_sense = ns;                 \
      } else {                                              \
        while (*(volatile unsigned*)&g_sense != ns)         \
          __nanosleep(20);                                  \
      }                                                     \
      __threadfence();                                      \
      s_sense = ns;                                         \
    }                                                       \
    __syncthreads();                                        \
  } while (0)

  GBAR();  // h0(0), h1(-1) visible everywhere

  const int bt = tid & 31;   // 4 b's: b = 4*bt .. 4*bt+3
  const int s = tid >> 5;    // k-slice of 32 (16 warps)
  const int gg = tid >> 5;   // reduce group for tid<256
  const int rb0 = (tid & 31) * 4;

  for (int t = 0; t < Tt; ++t) {
    const int p = t & 1;
    const float4* H0 = (const float4*)g_h0[p];        // h0(t)
    const float4* H1p = (const float4*)g_h1[p ^ 1];   // h1(t-1)
    float* h0n = g_h0[p ^ 1];                         // h0(t+1)
    float* h1c = g_h1[p];                             // h1(t)

    // deferred ys store for step t-1 (overlaps with this step's GEMM;
    // outside any fence — only fc_kernel reads ys, after rec completes)
    if (t > 0 && tid < 256 && gg >= 4) {
      float* ysPrev = g_ysT + (size_t)(t - 1) * (Ht * Bt);
      *(float4*)&ysPrev[(jb + gg - 4) * Bt + rb0] = ysReg;
    }

    if (tid < Bt) {
      int tn = (t + 1 < Tt) ? t + 1 : Tt - 1;
      srcsh[tid] = g_srcT[tn * Bt + tid];             // coalesced
    }

    // ---- fused GEMMs: accN = h0(t)@Whh0 ; accO = h0(t)@Wxh1 + h1(t-1)@Whh1
    {
      float4 z = make_float4(0, 0, 0, 0);
      float4 n0 = z, n1 = z, n2 = z, n3 = z;
      float4 o0 = z, o1 = z, o2 = z, o3 = z;
#pragma unroll 8
      for (int kk = 0; kk < 32; ++kk) {
        int k = s * 32 + kk;
        float4 ha = H0[k * 32 + bt];
        float4 hb = H1p[k * 32 + bt];
        float4 w0 = Wsh0[k];
        float4 w1 = Wsh1[k];
        float4 w2 = Wsh2[k];
        fma16(n0, n1, n2, n3, w0, ha);
        fma16(o0, o1, o2, o3, w1, ha);
        fma16(o0, o1, o2, o3, w2, hb);
      }
      red4[s * 256 + 0 * 32 + bt] = n0;
      red4[s * 256 + 1 * 32 + bt] = n1;
      red4[s * 256 + 2 * 32 + bt] = n2;
      red4[s * 256 + 3 * 32 + bt] = n3;
      red4[s * 256 + 4 * 32 + bt] = o0;
      red4[s * 256 + 5 * 32 + bt] = o1;
      red4[s * 256 + 6 * 32 + bt] = o2;
      red4[s * 256 + 7 * 32 + bt] = o3;
    }
    __syncthreads();

    // ---- reduce (tid < 256): thread -> group gg, rb0 (4 b's) ----
    if (tid < 256) {
      int g = gg, bt2 = tid & 31;
      int b0 = rb0;
      float4 sm = red4[g * 32 + bt2];
#pragma unroll
      for (int s2 = 1; s2 < 16; ++s2) {
        float4 r = red4[s2 * 256 + g * 32 + bt2];
        sm.x += r.x; sm.y += r.y; sm.z += r.z; sm.w += r.w;
      }
      int l0 = lensh[b0], l1 = lensh[b0 + 1], l2 = lensh[b0 + 2],
          l3 = lensh[b0 + 3];
      if (g < 4) {  // h0(t+1)
        int c = g;
        sm.x += Psh[srcsh[b0] * 4 + c];
        sm.y += Psh[srcsh[b0 + 1] * 4 + c];
        sm.z += Psh[srcsh[b0 + 2] * 4 + c];
        sm.w += Psh[srcsh[b0 + 3] * 4 + c];
        float4 nv;
        nv.x = (t + 1 < l0) ? tanhf(sm.x) : prevReg.x;
        nv.y = (t + 1 < l1) ? tanhf(sm.y) : prevReg.y;
        nv.z = (t + 1 < l2) ? tanhf(sm.z) : prevReg.z;
        nv.w = (t + 1 < l3) ? tanhf(sm.w) : prevReg.w;
        prevReg = nv;
        *(float4*)&h0n[(jb + c) * Bt + b0] = nv;
      } else {  // h1(t); ys store deferred to next iteration
        int c = g - 4;
        float bv = bsh[c];
        sm.x += bv; sm.y += bv; sm.z += bv; sm.w += bv;
        float4 nv;
        nv.x = (t < l0) ? tanhf(sm.x) : prevReg.x;
        nv.y = (t < l1) ? tanhf(sm.y) : prevReg.y;
        nv.z = (t < l2) ? tanhf(sm.z) : prevReg.z;
        nv.w = (t < l3) ? tanhf(sm.w) : prevReg.w;
        prevReg = nv;
        ysReg = nv;
        *(float4*)&h1c[(jb + c) * Bt + b0] = nv;
      }
    }
    GBAR();  // publish h0(t+1), h1(t); protects red/srcsh reuse
  }
#undef GBAR

  // epilogue: final ys store (t = 511)
  if (tid < 256 && gg >= 4) {
    float* ysLast = g_ysT + (size_t)(Tt - 1) * (Ht * Bt);
    *(float4*)&ysLast[(jb + gg - 4) * Bt + rb0] = ysReg;
  }
}

// ---------------- kernel 3: logits = ys @ fc_w + fc_b ----------------
__global__ __launch_bounds__(256) void fc_kernel(const float* __restrict__ fcw,
                                                 const float* __restrict__ fcb,
                                                 float* __restrict__ out) {
  __shared__ float4 Ash[32 * 32];
  __shared__ float4 Bsh[32 * 16];
  const int t = blockIdx.y;
  const int pt = blockIdx.x;
  const int tid = threadIdx.x;
  const int pq = tid & 15;
  const int bq = tid >> 4;
  const float4* ys4 = (const float4*)g_ysT + (size_t)t * (Ht * Bt / 4);
  const float4* w4 = (const float4*)fcw;

  float4 acc[8];
#pragma unroll
  for (int i = 0; i < 8; ++i) acc[i] = make_float4(0, 0, 0, 0);

  for (int k0 = 0; k0 < Ht; k0 += 32) {
#pragma unroll
    for (int i = 0; i < 4; ++i) {
      int idx = tid + i * 256;
      int kk = idx >> 5, b4 = idx & 31;
      Ash[idx] = ys4[(k0 + kk) * 32 + b4];
    }
#pragma unroll
    for (int i = 0; i < 2; ++i) {
      int idx = tid + i * 256;
      int kk = idx >> 4, p4 = idx & 15;
      Bsh[idx] = w4[(k0 + kk) * (VPt / 4) + pt * 16 + p4];
    }
    __syncthreads();
#pragma unroll
    for (int kk = 0; kk < 32; ++kk) {
      float4 wv = Bsh[kk * 16 + pq];
      float4 hA = Ash[kk * 32 + bq * 2];
      float4 hB = Ash[kk * 32 + bq * 2 + 1];
      float hb[8] = {hA.x, hA.y, hA.z, hA.w, hB.x, hB.y, hB.z, hB.w};
#pragma unroll
      for (int i = 0; i < 8; ++i) {
        acc[i].x = fmaf(hb[i], wv.x, acc[i].x);
        acc[i].y = fmaf(hb[i], wv.y, acc[i].y);
        acc[i].z = fmaf(hb[i], wv.z, acc[i].z);
        acc[i].w = fmaf(hb[i], wv.w, acc[i].w);
      }
    }
    __syncthreads();
  }
  float4 bv = ((const float4*)fcb)[pt * 16 + pq];
  float4* out4 = (float4*)out;
#pragma unroll
  for (int i = 0; i < 8; ++i) {
    int b = bq * 8 + i;
    float4 v;
    v.x = acc[i].x + bv.x;
    v.y = acc[i].y + bv.y;
    v.z = acc[i].z + bv.z;
    v.w = acc[i].w + bv.w;
    out4[((size_t)b * Tt + t) * (VPt / 4) + pt * 16 + pq] = v;
  }
}

extern "C" void kernel_launch(void* const* d_in, const int* in_sizes, int n_in,
                              void* d_out, int out_size) {
  const int* src = (const int*)d_in[0];
  const int* lens = (const int*)d_in[1];
  const float* emb = (const float*)d_in[2];
  const float* Wxh0 = (const float*)d_in[3];
  const float* bxh0 = (const float*)d_in[4];
  const float* Whh0 = (const float*)d_in[5];
  const float* Wxh1 = (const float*)d_in[6];
  const float* bxh1 = (const float*)d_in[7];
  const float* Whh1 = (const float*)d_in[8];
  const float* fcw = (const float*)d_in[9];
  const float* fcb = (const float*)d_in[10];

  const int smem_bytes = 3 * 8192 + 65536 + 1024;  // 91136
  cudaFuncSetAttribute(rec_kernel, cudaFuncAttributeMaxDynamicSharedMemorySize,
                       smem_bytes);

  srcT_kernel<<<256, 256>>>(src);
  proj_kernel<<<dim3(VCt, 4), 128>>>(emb, Wxh0, bxh0);
  rec_kernel<<<NCTA, NTHR, smem_bytes>>>(lens, Whh0, Wxh1, bxh1, Whh1);
  fc_kernel<<<dim3(2, Tt), 256>>>(fcw, fcb, (float*)d_out);
}